// round 7
// baseline (speedup 1.0000x reference)
#include <cuda_runtime.h>
#include <cuda_fp16.h>
#include <cuda_bf16.h>
#include <cstddef>

// Problem constants
#define B_   4
#define D_   256
#define E_   512
#define C_   256
#define NEG_INF -1e9f

typedef unsigned long long ull;

// Scratch (no cudaMalloc allowed)
__device__ __half g_enc_proj[B_ * E_ * C_];   // [b, e, o] half
__device__ __half g_dec_proj[B_ * D_ * C_];   // [b, d, o] half
__device__ float  g_scores[B_ * D_ * E_];     // [b, d, e]

__device__ __forceinline__ __half2 tanh2h(__half2 x) {
    unsigned int r, xi = *reinterpret_cast<unsigned int*>(&x);
    asm("tanh.approx.f16x2 %0, %1;" : "=r"(r) : "r"(xi));
    return *reinterpret_cast<__half2*>(&r);
}
__device__ __forceinline__ __half2 u2h(unsigned int u) {
    return *reinterpret_cast<__half2*>(&u);
}

// ---- packed f32x2 helpers (sm_103a FFMA2 path) ----
__device__ __forceinline__ ull pk2(float lo, float hi) {
    ull r; asm("mov.b64 %0, {%1, %2};" : "=l"(r) : "f"(lo), "f"(hi)); return r;
}
__device__ __forceinline__ void upk2(ull u, float& lo, float& hi) {
    asm("mov.b64 {%0, %1}, %2;" : "=f"(lo), "=f"(hi) : "l"(u));
}
__device__ __forceinline__ ull fma2_(ull a, ull b, ull c) {
    ull d; asm("fma.rn.f32x2 %0, %1, %2, %3;" : "=l"(d) : "l"(a), "l"(b), "l"(c)); return d;
}
__device__ __forceinline__ ull add2_(ull a, ull b) {
    ull d; asm("add.rn.f32x2 %0, %1, %2;" : "=l"(d) : "l"(a), "l"(b)); return d;
}
__device__ __forceinline__ ull mul2_(ull a, ull b) {
    ull d; asm("mul.rn.f32x2 %0, %1, %2;" : "=l"(d) : "l"(a), "l"(b)); return d;
}

// ---------------------------------------------------------------------------
// Fused GEMM: out[b,r,o] = sum_c X[b,r,c] * W[o,c], output stored as half.
// Tile 64x32, BK=16, 128 threads, 4x4 micro-tile, FFMA2 (f32x2) inner loop.
// ---------------------------------------------------------------------------
__global__ __launch_bounds__(128) void gemm_fused_kernel(
        const float* __restrict__ enc, const float* __restrict__ dec,
        const float* __restrict__ W1,  const float* __restrict__ W2) {
    __shared__ float Xs[16][68];
    __shared__ float Ws[16][36];

    const int b  = blockIdx.z;
    const int yt = blockIdx.y;
    const bool is_enc = (yt < 8);
    const int R      = is_enc ? E_ : D_;
    const int row0   = (is_enc ? yt : yt - 8) * 64;
    const int col0   = blockIdx.x * 32;
    const float* X   = is_enc ? enc : dec;
    const float* W   = is_enc ? W1  : W2;
    __half* out      = is_enc ? g_enc_proj : g_dec_proj;

    const int t  = threadIdx.x;
    const int lr = t >> 2;           // 0..31
    const int lc = (t & 3) << 2;     // 0,4,8,12
    const int ty = t >> 3;           // 0..15
    const int tx = t & 7;            // 0..7

    const float* Xb = X + ((size_t)b * R + row0 + lr) * C_ + lc;
    const float* Wb = W + (size_t)(col0 + lr) * C_ + lc;

    float4 xa0 = *(const float4*)Xb;
    float4 xa1 = *(const float4*)(Xb + 32 * C_);
    float4 wa  = *(const float4*)Wb;

    ull acc2[4][2];
#pragma unroll
    for (int i = 0; i < 4; i++) { acc2[i][0] = 0ull; acc2[i][1] = 0ull; }

    for (int k0 = 0; k0 < C_; k0 += 16) {
        Xs[lc + 0][lr] = xa0.x; Xs[lc + 1][lr] = xa0.y;
        Xs[lc + 2][lr] = xa0.z; Xs[lc + 3][lr] = xa0.w;
        Xs[lc + 0][lr + 32] = xa1.x; Xs[lc + 1][lr + 32] = xa1.y;
        Xs[lc + 2][lr + 32] = xa1.z; Xs[lc + 3][lr + 32] = xa1.w;
        Ws[lc + 0][lr] = wa.x; Ws[lc + 1][lr] = wa.y;
        Ws[lc + 2][lr] = wa.z; Ws[lc + 3][lr] = wa.w;
        __syncthreads();
        if (k0 + 16 < C_) {
            xa0 = *(const float4*)(Xb + k0 + 16);
            xa1 = *(const float4*)(Xb + 32 * C_ + k0 + 16);
            wa  = *(const float4*)(Wb + k0 + 16);
        }
#pragma unroll
        for (int kk = 0; kk < 16; kk++) {
            float4 a4 = *(const float4*)&Xs[kk][ty * 4];
            float4 b4 = *(const float4*)&Ws[kk][tx * 4];
            ull bp0 = pk2(b4.x, b4.y);
            ull bp1 = pk2(b4.z, b4.w);
            float a[4] = {a4.x, a4.y, a4.z, a4.w};
#pragma unroll
            for (int i = 0; i < 4; i++) {
                ull ai = pk2(a[i], a[i]);
                acc2[i][0] = fma2_(ai, bp0, acc2[i][0]);
                acc2[i][1] = fma2_(ai, bp1, acc2[i][1]);
            }
        }
        __syncthreads();
    }

#pragma unroll
    for (int i = 0; i < 4; i++) {
        float f0, f1, f2, f3;
        upk2(acc2[i][0], f0, f1);
        upk2(acc2[i][1], f2, f3);
        __half2 h0 = __floats2half2_rn(f0, f1);
        __half2 h1 = __floats2half2_rn(f2, f3);
        uint2 pkv = make_uint2(*reinterpret_cast<unsigned int*>(&h0),
                               *reinterpret_cast<unsigned int*>(&h1));
        *(uint2*)(out + ((size_t)b * R + row0 + ty * 4 + i) * C_ + col0 + tx * 4) = pkv;
    }
}

// ---------------------------------------------------------------------------
// Scores hybrid: s[b,d,e] = sum_c tanh(dec+enc)*v.
// Per 8-c group: c%8 in {0..5} -> MUFU tanh.f16x2; c%8 in {6,7} -> FMA-pipe
// f32x2 tanh via 2^y identity (magic rint + deg-4 2^f Taylor + int exponent
// scale on ALU + bit-trick reciprocal + 2 Newton). Pipes overlap in one loop.
// CTA tile 16 d x 64 e, 256 threads; thread (d_loc, e_loc) does 4 e's.
// ---------------------------------------------------------------------------
#define ETILE 64
#define DTILE 16
#define PIT 132
#define SCORES_SMEM ((ETILE * PIT + DTILE * PIT + 128 + 64 + 8) * 4)

__global__ __launch_bounds__(256) void scores_kernel(const float* __restrict__ v_g) {
    extern __shared__ unsigned int smu[];
    unsigned int* ep  = smu;                        // 64 rows x PIT
    unsigned int* dpu = ep + ETILE * PIT;           // 16 rows x PIT
    unsigned int* vsu = dpu + DTILE * PIT;          // 128 half2 (h2 v)
    float2* vf2 = (float2*)(vsu + 128);             // 32 fp32 pairs (c%8 in {6,7})

    const int b  = blockIdx.z;
    const int d0 = blockIdx.y * DTILE;
    const int e0 = blockIdx.x * ETILE;
    const int t  = threadIdx.x;

    const __half* encb = g_enc_proj + ((size_t)b * E_ + e0) * C_;
    for (int i = t; i < ETILE * 32; i += 256) {
        int r = i >> 5, q = i & 31;
        uint4 s = ((const uint4*)encb)[r * 32 + q];
        *(uint4*)(ep + r * PIT + q * 4) = s;
    }
    const __half* decb = g_dec_proj + ((size_t)b * D_ + d0) * C_;
    for (int i = t; i < DTILE * 32; i += 256) {
        int r = i >> 5, q = i & 31;
        uint4 s = ((const uint4*)decb)[r * 32 + q];
        *(uint4*)(dpu + r * PIT + q * 4) = s;
    }
    if (t < 128) {
        float2 vf = ((const float2*)v_g)[t];
        __half2 vh = __floats2half2_rn(vf.x, vf.y);
        vsu[t] = *reinterpret_cast<unsigned int*>(&vh);
    }
    if (t < 32) {
        vf2[t] = make_float2(v_g[8 * t + 6], v_g[8 * t + 7]);
    }
    __syncthreads();

    const int d_loc = t >> 4;
    const int e_loc = t & 15;
    const unsigned int* dpr = dpu + d_loc * PIT;
    const unsigned int* epb = ep + e_loc * PIT;

    // packed constants for the f32x2 tanh path
    const ull K2     = pk2(2.8853900817779268f, 2.8853900817779268f); // 2*log2(e)
    const ull MAG2   = pk2(12582912.0f, 12582912.0f);
    const ull NMAG2  = pk2(-12582912.0f, -12582912.0f);
    const ull NONE2  = pk2(-1.0f, -1.0f);
    const ull ONE2   = pk2(1.0f, 1.0f);
    const ull TWO2   = pk2(2.0f, 2.0f);
    const ull NTWO2  = pk2(-2.0f, -2.0f);
    const ull C1     = pk2(0.69314718f, 0.69314718f);
    const ull C2     = pk2(0.24022651f, 0.24022651f);
    const ull C3     = pk2(0.05550411f, 0.05550411f);
    const ull C4     = pk2(0.00961813f, 0.00961813f);
    const int MCLO = 0x4B400000 - 30, MCHI = 0x4B400000 + 30;
    const int SBIAS = 127 - 0x4B400000;

    __half2 a2[4];
    ull facc2[4];
    float facc[4];
#pragma unroll
    for (int j = 0; j < 4; j++) {
        a2[j] = __floats2half2_rn(0.f, 0.f);
        facc2[j] = 0ull;
        facc[j] = 0.f;
    }

    for (int g = 0; g < 32; g++) {
        uint4 du = *(const uint4*)(dpr + 4 * g);
        uint4 vu = *(const uint4*)(vsu + 4 * g);
        float2 vp = vf2[g];
        ull v2 = pk2(vp.x, vp.y);
        __half2 dh0 = u2h(du.x), dh1 = u2h(du.y), dh2 = u2h(du.z), dhw = u2h(du.w);
        __half2 vv0 = u2h(vu.x), vv1 = u2h(vu.y), vv2 = u2h(vu.z);
#pragma unroll
        for (int j = 0; j < 4; j++) {
            uint4 eu = *(const uint4*)(epb + j * (16 * PIT) + 4 * g);
            // MUFU path: 6 c's
            __half2 s = a2[j];
            s = __hfma2(tanh2h(__hadd2(dh0, u2h(eu.x))), vv0, s);
            s = __hfma2(tanh2h(__hadd2(dh1, u2h(eu.y))), vv1, s);
            s = __hfma2(tanh2h(__hadd2(dh2, u2h(eu.z))), vv2, s);
            a2[j] = s;
            // FMA-pipe path: 2 c's, fp32x2
            __half2 sw = __hadd2(dhw, u2h(eu.w));
            ull y2 = mul2_(pk2(__low2float(sw), __high2float(sw)), K2);
            ull m2 = add2_(y2, MAG2);
            int il = (int)(unsigned)m2;
            int ih = (int)(unsigned)(m2 >> 32);
            il = il < MCLO ? MCLO : (il > MCHI ? MCHI : il);
            ih = ih < MCLO ? MCLO : (ih > MCHI ? MCHI : ih);
            ull mc2 = ((ull)(unsigned)ih << 32) | (unsigned)il;
            ull nf2 = add2_(mc2, NMAG2);              // n as float pair
            ull f2  = fma2_(nf2, NONE2, y2);          // f = y - n
            ull p2  = fma2_(f2, C4, C3);
            p2 = fma2_(f2, p2, C2);
            p2 = fma2_(f2, p2, C1);
            p2 = fma2_(f2, p2, ONE2);                 // 2^f
            unsigned slo = (unsigned)((il + SBIAS) << 23);
            unsigned shi = (unsigned)((ih + SBIAS) << 23);
            ull s2 = ((ull)shi << 32) | slo;          // 2^n as float pair
            ull E2   = mul2_(p2, s2);                 // e^{2x}
            ull den2 = add2_(E2, ONE2);
            unsigned rlo = 0x7EF311C3u - (unsigned)den2;
            unsigned rhi = 0x7EF311C3u - (unsigned)(den2 >> 32);
            ull r0  = ((ull)rhi << 32) | rlo;         // ~1/den
            ull u1  = fma2_(den2, r0, NTWO2);         // d*r - 2
            ull r1n = mul2_(r0, u1);                  // -r1
            ull uu2 = fma2_(den2, r1n, TWO2);         // 2 - d*r1
            ull r2n = mul2_(r1n, uu2);                // -r2
            ull t2  = fma2_(r2n, TWO2, ONE2);         // tanh = 1 - 2*r2
            facc2[j] = fma2_(t2, v2, facc2[j]);
        }
        if ((g & 3) == 3) {
#pragma unroll
            for (int j = 0; j < 4; j++) {
                float2 f = __half22float2(a2[j]);
                facc[j] += f.x + f.y;
                a2[j] = __floats2half2_rn(0.f, 0.f);
            }
        }
    }

#pragma unroll
    for (int j = 0; j < 4; j++) {
        float plo, phi;
        upk2(facc2[j], plo, phi);
        facc[j] += plo + phi;
    }

    float* srow = g_scores + ((size_t)b * D_ + d0 + d_loc) * E_ + e0 + e_loc;
#pragma unroll
    for (int j = 0; j < 4; j++) srow[16 * j] = facc[j];
}

// ---------------------------------------------------------------------------
// Masked log-softmax, one warp per row (E=512, 16 elems/lane).
// ---------------------------------------------------------------------------
__global__ __launch_bounds__(256) void softmax_kernel(const int* __restrict__ mask,
                                                      float* __restrict__ out) {
    const int row  = blockIdx.x * 8 + (threadIdx.x >> 5);
    const int lane = threadIdx.x & 31;

    const float4* s = (const float4*)(g_scores + (size_t)row * E_);
    const int4*   m = (const int4*)(mask + (size_t)row * E_);

    float x[16];
    float vmax = -3.0e38f;
#pragma unroll
    for (int q = 0; q < 4; q++) {
        float4 sv = s[q * 32 + lane];
        int4   mv = m[q * 32 + lane];
        x[4 * q + 0] = mv.x ? sv.x : NEG_INF;
        x[4 * q + 1] = mv.y ? sv.y : NEG_INF;
        x[4 * q + 2] = mv.z ? sv.z : NEG_INF;
        x[4 * q + 3] = mv.w ? sv.w : NEG_INF;
        vmax = fmaxf(vmax, fmaxf(fmaxf(x[4 * q], x[4 * q + 1]),
                                 fmaxf(x[4 * q + 2], x[4 * q + 3])));
    }
#pragma unroll
    for (int o = 16; o; o >>= 1)
        vmax = fmaxf(vmax, __shfl_xor_sync(0xffffffffu, vmax, o));

    float sum = 0.f;
#pragma unroll
    for (int k = 0; k < 16; k++) sum += __expf(x[k] - vmax);
#pragma unroll
    for (int o = 16; o; o >>= 1)
        sum += __shfl_xor_sync(0xffffffffu, sum, o);

    const float lse = vmax + logf(sum);

    float* orow = out + (size_t)row * E_;
#pragma unroll
    for (int q = 0; q < 4; q++) {
        float4 o4 = make_float4(x[4 * q] - lse, x[4 * q + 1] - lse,
                                x[4 * q + 2] - lse, x[4 * q + 3] - lse);
        ((float4*)orow)[q * 32 + lane] = o4;
    }
}

// ---------------------------------------------------------------------------
extern "C" void kernel_launch(void* const* d_in, const int* in_sizes, int n_in,
                              void* d_out, int out_size) {
    const float* decoder = (const float*)d_in[0];
    const float* encoder = (const float*)d_in[1];
    const int*   mask    = (const int*)d_in[2];
    const float* W1      = (const float*)d_in[3];
    const float* W2      = (const float*)d_in[4];
    const float* v       = (const float*)d_in[5];
    float* out           = (float*)d_out;

    cudaFuncSetAttribute(scores_kernel,
                         cudaFuncAttributeMaxDynamicSharedMemorySize, SCORES_SMEM);

    gemm_fused_kernel<<<dim3(8, 12, B_), 128>>>(encoder, decoder, W1, W2);
    scores_kernel<<<dim3(E_ / ETILE, D_ / DTILE, B_), 256, SCORES_SMEM>>>(v);
    softmax_kernel<<<B_ * D_ / 8, 256>>>(mask, out);
}

// round 8
// speedup vs baseline: 1.0669x; 1.0669x over previous
#include <cuda_runtime.h>
#include <cuda_fp16.h>
#include <cuda_bf16.h>
#include <cstddef>

#define B_   4
#define D_   256
#define E_   512
#define C_   256
#define NEG_INF -1e9f

typedef unsigned long long ull;

// Scratch. Per projection row of 256 c's: c%8 in {0..3} -> raw proj as half
// (128 halves, "h" buffer); c%8 in {4..7} -> tanh(proj) as f32 (128 floats, "f").
__device__ __half g_enc_h[B_ * E_ * 128];
__device__ float  g_enc_f[B_ * E_ * 128];
__device__ __half g_dec_h[B_ * D_ * 128];
__device__ float  g_dec_f[B_ * D_ * 128];
__device__ float  g_scores[B_ * D_ * E_];

__device__ __forceinline__ __half2 tanh2h(__half2 x) {
    unsigned int r, xi = *reinterpret_cast<unsigned int*>(&x);
    asm("tanh.approx.f16x2 %0, %1;" : "=r"(r) : "r"(xi));
    return *reinterpret_cast<__half2*>(&r);
}
__device__ __forceinline__ __half2 u2h(unsigned int u) {
    return *reinterpret_cast<__half2*>(&u);
}
__device__ __forceinline__ float tanhf_fast(float x) {
    float y; asm("tanh.approx.f32 %0, %1;" : "=f"(y) : "f"(x)); return y;
}
__device__ __forceinline__ ull fma2_(ull a, ull b, ull c) {
    ull d; asm("fma.rn.f32x2 %0, %1, %2, %3;" : "=l"(d) : "l"(a), "l"(b), "l"(c)); return d;
}
__device__ __forceinline__ ull add2_(ull a, ull b) {
    ull d; asm("add.rn.f32x2 %0, %1, %2;" : "=l"(d) : "l"(a), "l"(b)); return d;
}
__device__ __forceinline__ ull mul2_(ull a, ull b) {
    ull d; asm("mul.rn.f32x2 %0, %1, %2;" : "=l"(d) : "l"(a), "l"(b)); return d;
}

#define ONE2_  0x3F8000003F800000ull
#define TWO2_  0x4000000040000000ull
#define NTWO2_ 0xC0000000C0000000ull

// tanh(a+b)*v accumulation via addition formula; ta, tb packed f32 pairs of
// tanh(a), tanh(b); nv = packed(-v). 8 fma-pipe instrs + 2 ALU per call.
__device__ __forceinline__ ull tanh_sum_acc(ull ta, ull tb, ull nv, ull acc) {
    ull num = add2_(ta, tb);
    ull den = fma2_(ta, tb, ONE2_);          // 1 + ta*tb  (in (0,2])
    ull r0;
    asm("{\n\t.reg .b32 lo, hi;\n\t"
        "mov.b64 {lo, hi}, %1;\n\t"
        "sub.u32 lo, 0x7EF311C3, lo;\n\t"
        "sub.u32 hi, 0x7EF311C3, hi;\n\t"
        "mov.b64 %0, {lo, hi};\n\t}" : "=l"(r0) : "l"(den));
    ull u1  = fma2_(den, r0, NTWO2_);        // d*r0 - 2
    ull r1n = mul2_(r0, u1);                 // -r1
    ull u2  = fma2_(den, r1n, TWO2_);        // 2 - d*r1
    ull r2n = mul2_(r1n, u2);                // -r2 ~ -1/den
    ull t   = mul2_(num, r2n);               // -tanh(a+b)
    return fma2_(t, nv, acc);                // + tanh*v
}

// ---------------------------------------------------------------------------
// Fused GEMM: tile 64x32, BK=16, 128 thr, 4x4 micro (R5 structure).
// Epilogue: tx even -> raw half2 to *_h; tx odd -> tanhf as f32 to *_f.
// ---------------------------------------------------------------------------
__global__ __launch_bounds__(128) void gemm_fused_kernel(
        const float* __restrict__ enc, const float* __restrict__ dec,
        const float* __restrict__ W1,  const float* __restrict__ W2) {
    __shared__ float Xs[16][68];
    __shared__ float Ws[16][36];

    const int b  = blockIdx.z;
    const int yt = blockIdx.y;
    const bool is_enc = (yt < 8);
    const int R      = is_enc ? E_ : D_;
    const int row0   = (is_enc ? yt : yt - 8) * 64;
    const int col0   = blockIdx.x * 32;
    const float* X   = is_enc ? enc : dec;
    const float* W   = is_enc ? W1  : W2;
    __half* outh     = is_enc ? g_enc_h : g_dec_h;
    float*  outf     = is_enc ? g_enc_f : g_dec_f;

    const int t  = threadIdx.x;
    const int lr = t >> 2;
    const int lc = (t & 3) << 2;
    const int ty = t >> 3;
    const int tx = t & 7;

    const float* Xb = X + ((size_t)b * R + row0 + lr) * C_ + lc;
    const float* Wb = W + (size_t)(col0 + lr) * C_ + lc;

    float4 xa0 = *(const float4*)Xb;
    float4 xa1 = *(const float4*)(Xb + 32 * C_);
    float4 wa  = *(const float4*)Wb;

    float acc[4][4];
#pragma unroll
    for (int i = 0; i < 4; i++)
#pragma unroll
        for (int j = 0; j < 4; j++) acc[i][j] = 0.f;

    for (int k0 = 0; k0 < C_; k0 += 16) {
        Xs[lc + 0][lr] = xa0.x; Xs[lc + 1][lr] = xa0.y;
        Xs[lc + 2][lr] = xa0.z; Xs[lc + 3][lr] = xa0.w;
        Xs[lc + 0][lr + 32] = xa1.x; Xs[lc + 1][lr + 32] = xa1.y;
        Xs[lc + 2][lr + 32] = xa1.z; Xs[lc + 3][lr + 32] = xa1.w;
        Ws[lc + 0][lr] = wa.x; Ws[lc + 1][lr] = wa.y;
        Ws[lc + 2][lr] = wa.z; Ws[lc + 3][lr] = wa.w;
        __syncthreads();
        if (k0 + 16 < C_) {
            xa0 = *(const float4*)(Xb + k0 + 16);
            xa1 = *(const float4*)(Xb + 32 * C_ + k0 + 16);
            wa  = *(const float4*)(Wb + k0 + 16);
        }
#pragma unroll
        for (int kk = 0; kk < 16; kk++) {
            float4 a4 = *(const float4*)&Xs[kk][ty * 4];
            float4 b4 = *(const float4*)&Ws[kk][tx * 4];
            float a[4] = {a4.x, a4.y, a4.z, a4.w};
            float bb[4] = {b4.x, b4.y, b4.z, b4.w};
#pragma unroll
            for (int i = 0; i < 4; i++)
#pragma unroll
                for (int j = 0; j < 4; j++)
                    acc[i][j] = fmaf(a[i], bb[j], acc[i][j]);
        }
        __syncthreads();
    }

#pragma unroll
    for (int i = 0; i < 4; i++) {
        const size_t r = (size_t)b * R + row0 + ty * 4 + i;
        if ((tx & 1) == 0) {
            __half2 h0 = __floats2half2_rn(acc[i][0], acc[i][1]);
            __half2 h1 = __floats2half2_rn(acc[i][2], acc[i][3]);
            uint2 pk = make_uint2(*reinterpret_cast<unsigned int*>(&h0),
                                  *reinterpret_cast<unsigned int*>(&h1));
            *(uint2*)(outh + r * 128 + (col0 >> 1) + tx * 2) = pk;
        } else {
            float4 tq = make_float4(tanhf_fast(acc[i][0]), tanhf_fast(acc[i][1]),
                                    tanhf_fast(acc[i][2]), tanhf_fast(acc[i][3]));
            *(float4*)(outf + r * 128 + (col0 >> 1) + tx * 2 - 2) = tq;
        }
    }
}

// ---------------------------------------------------------------------------
// Scores hybrid v2: c%8 {0..3} on MUFU (h2 raw), {4..7} on FMA pipe (f32
// tanh'd, addition formula). CTA 32d x 64e, 256 thr.
// Thread (dg = t>>5, el = t&31): 4 d's x 2 e's (el, el+32).
// ---------------------------------------------------------------------------
#define EPH_O 0
#define EPF_O (64 * 66)
#define DPH_O (EPF_O + 64 * 132)
#define DPF_O (DPH_O + 32 * 66)
#define VH_O  (DPF_O + 32 * 132)
#define VFN_O (VH_O + 64)
#define SCORES_SMEM ((VFN_O + 128) * 4)

__global__ __launch_bounds__(256, 2) void scores_kernel(const float* __restrict__ v_g) {
    extern __shared__ unsigned int smu[];
    unsigned int* eph = smu + EPH_O;            // 64 x 66 h2 words
    float*        epf = (float*)(smu + EPF_O);  // 64 x 132 f32
    unsigned int* dph = smu + DPH_O;            // 32 x 66
    float*        dpf = (float*)(smu + DPF_O);  // 32 x 132
    unsigned int* vh  = smu + VH_O;             // 64 h2 words
    float*        vfn = (float*)(smu + VFN_O);  // 128 f32 (-v)

    const int b  = blockIdx.z;
    const int d0 = blockIdx.y * 32;
    const int e0 = blockIdx.x * 64;
    const int t  = threadIdx.x;

    const __half* ehsrc = g_enc_h + ((size_t)b * E_ + e0) * 128;
    for (int i = t; i < 64 * 32; i += 256) {
        int r = i >> 5, q = i & 31;
        uint2 s = ((const uint2*)ehsrc)[r * 32 + q];
        *(uint2*)(eph + r * 66 + q * 2) = s;
    }
    const float* efsrc = g_enc_f + ((size_t)b * E_ + e0) * 128;
    for (int i = t; i < 64 * 32; i += 256) {
        int r = i >> 5, q = i & 31;
        uint4 s = ((const uint4*)efsrc)[r * 32 + q];
        *(uint4*)(epf + r * 132 + q * 4) = s;
    }
    const __half* dhsrc = g_dec_h + ((size_t)b * D_ + d0) * 128;
    for (int i = t; i < 32 * 32; i += 256) {
        int r = i >> 5, q = i & 31;
        uint2 s = ((const uint2*)dhsrc)[r * 32 + q];
        *(uint2*)(dph + r * 66 + q * 2) = s;
    }
    const float* dfsrc = g_dec_f + ((size_t)b * D_ + d0) * 128;
    for (int i = t; i < 32 * 32; i += 256) {
        int r = i >> 5, q = i & 31;
        uint4 s = ((const uint4*)dfsrc)[r * 32 + q];
        *(uint4*)(dpf + r * 132 + q * 4) = s;
    }
    if (t < 64) {
        int g = t >> 1, h = t & 1;
        int c0 = 8 * g + 2 * h;
        __half2 p = __floats2half2_rn(v_g[c0], v_g[c0 + 1]);
        vh[t] = *reinterpret_cast<unsigned int*>(&p);
    }
    if (t < 128) {
        vfn[t] = -v_g[(t >> 2) * 8 + 4 + (t & 3)];
    }
    __syncthreads();

    const int el = t & 31;
    const int dg = t >> 5;
    const unsigned int* eh0 = eph + el * 66;
    const unsigned int* eh1 = eph + (el + 32) * 66;
    const float* ef0 = epf + el * 132;
    const float* ef1 = epf + (el + 32) * 132;
    const unsigned int* dhb = dph + (dg * 4) * 66;
    const float* dfb = dpf + (dg * 4) * 132;

    __half2 ah[8];
    ull af[8];
    float facc[8];
#pragma unroll
    for (int p = 0; p < 8; p++) {
        ah[p] = __floats2half2_rn(0.f, 0.f);
        af[p] = 0ull;
        facc[p] = 0.f;
    }

    for (int g = 0; g < 32; g++) {
        uint2 vhp = *(const uint2*)(vh + 2 * g);
        __half2 v0 = u2h(vhp.x), v1 = u2h(vhp.y);
        ulonglong2 nv = *(const ulonglong2*)(vfn + 4 * g);
        uint2 e0h = *(const uint2*)(eh0 + 2 * g);
        uint2 e1h = *(const uint2*)(eh1 + 2 * g);
        ulonglong2 e0f = *(const ulonglong2*)(ef0 + 4 * g);
        ulonglong2 e1f = *(const ulonglong2*)(ef1 + 4 * g);
#pragma unroll
        for (int i = 0; i < 4; i++) {
            uint2 dh = *(const uint2*)(dhb + i * 66 + 2 * g);
            ulonglong2 df = *(const ulonglong2*)(dfb + i * 132 + 4 * g);
            __half2 dh0 = u2h(dh.x), dh1 = u2h(dh.y);
            __half2 s0 = ah[i * 2];
            s0 = __hfma2(tanh2h(__hadd2(dh0, u2h(e0h.x))), v0, s0);
            s0 = __hfma2(tanh2h(__hadd2(dh1, u2h(e0h.y))), v1, s0);
            ah[i * 2] = s0;
            __half2 s1 = ah[i * 2 + 1];
            s1 = __hfma2(tanh2h(__hadd2(dh0, u2h(e1h.x))), v0, s1);
            s1 = __hfma2(tanh2h(__hadd2(dh1, u2h(e1h.y))), v1, s1);
            ah[i * 2 + 1] = s1;
            ull a = af[i * 2];
            a = tanh_sum_acc(df.x, e0f.x, nv.x, a);
            a = tanh_sum_acc(df.y, e0f.y, nv.y, a);
            af[i * 2] = a;
            ull c = af[i * 2 + 1];
            c = tanh_sum_acc(df.x, e1f.x, nv.x, c);
            c = tanh_sum_acc(df.y, e1f.y, nv.y, c);
            af[i * 2 + 1] = c;
        }
        if ((g & 3) == 3) {
#pragma unroll
            for (int p = 0; p < 8; p++) {
                float2 f = __half22float2(ah[p]);
                facc[p] += f.x + f.y;
                ah[p] = __floats2half2_rn(0.f, 0.f);
            }
        }
    }

#pragma unroll
    for (int p = 0; p < 8; p++) {
        float lo, hi;
        asm("mov.b64 {%0, %1}, %2;" : "=f"(lo), "=f"(hi) : "l"(af[p]));
        facc[p] += lo + hi;
    }

#pragma unroll
    for (int i = 0; i < 4; i++) {
        float* srow = g_scores + ((size_t)b * D_ + d0 + dg * 4 + i) * E_ + e0 + el;
        srow[0]  = facc[i * 2];
        srow[32] = facc[i * 2 + 1];
    }
}

// ---------------------------------------------------------------------------
// Masked log-softmax, one warp per row (E=512, 16 elems/lane).
// ---------------------------------------------------------------------------
__global__ __launch_bounds__(256) void softmax_kernel(const int* __restrict__ mask,
                                                      float* __restrict__ out) {
    const int row  = blockIdx.x * 8 + (threadIdx.x >> 5);
    const int lane = threadIdx.x & 31;

    const float4* s = (const float4*)(g_scores + (size_t)row * E_);
    const int4*   m = (const int4*)(mask + (size_t)row * E_);

    float x[16];
    float vmax = -3.0e38f;
#pragma unroll
    for (int q = 0; q < 4; q++) {
        float4 sv = s[q * 32 + lane];
        int4   mv = m[q * 32 + lane];
        x[4 * q + 0] = mv.x ? sv.x : NEG_INF;
        x[4 * q + 1] = mv.y ? sv.y : NEG_INF;
        x[4 * q + 2] = mv.z ? sv.z : NEG_INF;
        x[4 * q + 3] = mv.w ? sv.w : NEG_INF;
        vmax = fmaxf(vmax, fmaxf(fmaxf(x[4 * q], x[4 * q + 1]),
                                 fmaxf(x[4 * q + 2], x[4 * q + 3])));
    }
#pragma unroll
    for (int o = 16; o; o >>= 1)
        vmax = fmaxf(vmax, __shfl_xor_sync(0xffffffffu, vmax, o));

    float sum = 0.f;
#pragma unroll
    for (int k = 0; k < 16; k++) sum += __expf(x[k] - vmax);
#pragma unroll
    for (int o = 16; o; o >>= 1)
        sum += __shfl_xor_sync(0xffffffffu, sum, o);

    const float lse = vmax + logf(sum);

    float* orow = out + (size_t)row * E_;
#pragma unroll
    for (int q = 0; q < 4; q++) {
        float4 o4 = make_float4(x[4 * q] - lse, x[4 * q + 1] - lse,
                                x[4 * q + 2] - lse, x[4 * q + 3] - lse);
        ((float4*)orow)[q * 32 + lane] = o4;
    }
}

// ---------------------------------------------------------------------------
extern "C" void kernel_launch(void* const* d_in, const int* in_sizes, int n_in,
                              void* d_out, int out_size) {
    const float* decoder = (const float*)d_in[0];
    const float* encoder = (const float*)d_in[1];
    const int*   mask    = (const int*)d_in[2];
    const float* W1      = (const float*)d_in[3];
    const float* W2      = (const float*)d_in[4];
    const float* v       = (const float*)d_in[5];
    float* out           = (float*)d_out;

    cudaFuncSetAttribute(scores_kernel,
                         cudaFuncAttributeMaxDynamicSharedMemorySize, SCORES_SMEM);

    gemm_fused_kernel<<<dim3(8, 12, B_), 128>>>(encoder, decoder, W1, W2);
    scores_kernel<<<dim3(E_ / 64, D_ / 32, B_), 256, SCORES_SMEM>>>(v);
    softmax_kernel<<<B_ * D_ / 8, 256>>>(mask, out);
}

// round 10
// speedup vs baseline: 1.0915x; 1.0230x over previous
#include <cuda_runtime.h>
#include <cuda_fp16.h>
#include <cuda_bf16.h>
#include <cstddef>

#define B_   4
#define D_   256
#define E_   512
#define C_   256
#define NEG_INF -1e9f

typedef unsigned long long ull;

// Scratch. h buffers: proj as half at natural col index (c%8 in {6,7} unused).
// f buffers: tanh(proj) as f32 for c%8 in {6,7}: index = (c>>3)*2 + (c&1).
__device__ __half g_enc_h[B_ * E_ * 256];
__device__ float  g_enc_f[B_ * E_ * 64];
__device__ __half g_dec_h[B_ * D_ * 256];
__device__ float  g_dec_f[B_ * D_ * 64];
__device__ float  g_scores[B_ * D_ * E_];

__device__ __forceinline__ __half2 tanh2h(__half2 x) {
    unsigned int r, xi = *reinterpret_cast<unsigned int*>(&x);
    asm("tanh.approx.f16x2 %0, %1;" : "=r"(r) : "r"(xi));
    return *reinterpret_cast<__half2*>(&r);
}
__device__ __forceinline__ __half2 u2h(unsigned int u) {
    return *reinterpret_cast<__half2*>(&u);
}
__device__ __forceinline__ float tanhf_fast(float x) {
    float y; asm("tanh.approx.f32 %0, %1;" : "=f"(y) : "f"(x)); return y;
}
__device__ __forceinline__ ull fma2_(ull a, ull b, ull c) {
    ull d; asm("fma.rn.f32x2 %0, %1, %2, %3;" : "=l"(d) : "l"(a), "l"(b), "l"(c)); return d;
}
__device__ __forceinline__ ull add2_(ull a, ull b) {
    ull d; asm("add.rn.f32x2 %0, %1, %2;" : "=l"(d) : "l"(a), "l"(b)); return d;
}
__device__ __forceinline__ ull mul2_(ull a, ull b) {
    ull d; asm("mul.rn.f32x2 %0, %1, %2;" : "=l"(d) : "l"(a), "l"(b)); return d;
}

#define ONE2_  0x3F8000003F800000ull
#define NTWO2_ 0xC0000000C0000000ull

// tanh(a+b)*v via addition formula, 1 Newton step.
// ta, tb = packed f32 tanh pairs; nv = packed(-v). 6 f32x2 + 2 ALU.
__device__ __forceinline__ ull tanh_sum_acc1(ull ta, ull tb, ull nv, ull acc) {
    ull num = add2_(ta, tb);
    ull den = fma2_(ta, tb, ONE2_);          // 1 + ta*tb in (0,2]
    ull r0;
    asm("{\n\t.reg .b32 lo, hi;\n\t"
        "mov.b64 {lo, hi}, %1;\n\t"
        "sub.u32 lo, 0x7EF311C3, lo;\n\t"
        "sub.u32 hi, 0x7EF311C3, hi;\n\t"
        "mov.b64 %0, {lo, hi};\n\t}" : "=l"(r0) : "l"(den));
    ull u1  = fma2_(den, r0, NTWO2_);        // d*r0 - 2
    ull r1n = mul2_(r0, u1);                 // -r1 ~ -1/den
    ull t   = mul2_(num, r1n);               // -tanh(a+b)
    return fma2_(t, nv, acc);                // acc + tanh*v
}

// ---------------------------------------------------------------------------
// Fused GEMM: tile 64x32, BK=16, 128 thr, 4x4 micro.
// Epilogue: tx even -> 4 halves (c%8 0..3); tx odd -> 2 halves (c%8 4,5)
// + 2 tanh'd f32 (c%8 6,7).
// ---------------------------------------------------------------------------
__global__ __launch_bounds__(128) void gemm_fused_kernel(
        const float* __restrict__ enc, const float* __restrict__ dec,
        const float* __restrict__ W1,  const float* __restrict__ W2) {
    __shared__ float Xs[16][68];
    __shared__ float Ws[16][36];

    const int b  = blockIdx.z;
    const int yt = blockIdx.y;
    const bool is_enc = (yt < 8);
    const int R      = is_enc ? E_ : D_;
    const int row0   = (is_enc ? yt : yt - 8) * 64;
    const int col0   = blockIdx.x * 32;
    const float* X   = is_enc ? enc : dec;
    const float* W   = is_enc ? W1  : W2;
    __half* outh     = is_enc ? g_enc_h : g_dec_h;
    float*  outf     = is_enc ? g_enc_f : g_dec_f;

    const int t  = threadIdx.x;
    const int lr = t >> 2;
    const int lc = (t & 3) << 2;
    const int ty = t >> 3;
    const int tx = t & 7;

    const float* Xb = X + ((size_t)b * R + row0 + lr) * C_ + lc;
    const float* Wb = W + (size_t)(col0 + lr) * C_ + lc;

    float4 xa0 = *(const float4*)Xb;
    float4 xa1 = *(const float4*)(Xb + 32 * C_);
    float4 wa  = *(const float4*)Wb;

    float acc[4][4];
#pragma unroll
    for (int i = 0; i < 4; i++)
#pragma unroll
        for (int j = 0; j < 4; j++) acc[i][j] = 0.f;

    for (int k0 = 0; k0 < C_; k0 += 16) {
        Xs[lc + 0][lr] = xa0.x; Xs[lc + 1][lr] = xa0.y;
        Xs[lc + 2][lr] = xa0.z; Xs[lc + 3][lr] = xa0.w;
        Xs[lc + 0][lr + 32] = xa1.x; Xs[lc + 1][lr + 32] = xa1.y;
        Xs[lc + 2][lr + 32] = xa1.z; Xs[lc + 3][lr + 32] = xa1.w;
        Ws[lc + 0][lr] = wa.x; Ws[lc + 1][lr] = wa.y;
        Ws[lc + 2][lr] = wa.z; Ws[lc + 3][lr] = wa.w;
        __syncthreads();
        if (k0 + 16 < C_) {
            xa0 = *(const float4*)(Xb + k0 + 16);
            xa1 = *(const float4*)(Xb + 32 * C_ + k0 + 16);
            wa  = *(const float4*)(Wb + k0 + 16);
        }
#pragma unroll
        for (int kk = 0; kk < 16; kk++) {
            float4 a4 = *(const float4*)&Xs[kk][ty * 4];
            float4 b4 = *(const float4*)&Ws[kk][tx * 4];
            float a[4] = {a4.x, a4.y, a4.z, a4.w};
            float bb[4] = {b4.x, b4.y, b4.z, b4.w};
#pragma unroll
            for (int i = 0; i < 4; i++)
#pragma unroll
                for (int j = 0; j < 4; j++)
                    acc[i][j] = fmaf(a[i], bb[j], acc[i][j]);
        }
        __syncthreads();
    }

    const int G = (col0 >> 3) + (tx >> 1);   // global c-group of this thread
#pragma unroll
    for (int i = 0; i < 4; i++) {
        const size_t r = (size_t)b * R + row0 + ty * 4 + i;
        if ((tx & 1) == 0) {
            // cols 8G..8G+3 -> h buffer
            __half2 h0 = __floats2half2_rn(acc[i][0], acc[i][1]);
            __half2 h1 = __floats2half2_rn(acc[i][2], acc[i][3]);
            uint2 pk = make_uint2(*reinterpret_cast<unsigned int*>(&h0),
                                  *reinterpret_cast<unsigned int*>(&h1));
            *(uint2*)(outh + r * 256 + 8 * G) = pk;
        } else {
            // cols 8G+4,8G+5 -> h; 8G+6,8G+7 -> tanh'd f32
            __half2 h4 = __floats2half2_rn(acc[i][0], acc[i][1]);
            *(unsigned int*)(outh + r * 256 + 8 * G + 4) =
                *reinterpret_cast<unsigned int*>(&h4);
            float2 tf = make_float2(tanhf_fast(acc[i][2]), tanhf_fast(acc[i][3]));
            *(float2*)(outf + r * 64 + 2 * G) = tf;
        }
    }
}

// ---------------------------------------------------------------------------
// Scores 6:2 hybrid: c%8 {0..5} on MUFU (h2), {6,7} on FMA pipe (f32
// addition formula, 1 Newton). CTA 32d x 64e, 256 thr.
// Thread (dg = t>>5, el = t&31): 4 d's x 2 e's (el, el+32).
// f pitch 66 words (conflict-free LDS.64); fills use uint2 (8B, alignment-safe).
// ---------------------------------------------------------------------------
#define EPH_O 0
#define EPF_O (64 * 132)
#define DPH_O (EPF_O + 64 * 66)
#define DPF_O (DPH_O + 32 * 132)
#define VH_O  (DPF_O + 32 * 66)
#define VFN_O (VH_O + 128)
#define SCORES_SMEM ((VFN_O + 64) * 4)

__global__ __launch_bounds__(256, 2) void scores_kernel(const float* __restrict__ v_g) {
    extern __shared__ unsigned int smu[];
    unsigned int* eph = smu + EPH_O;            // 64 x 132 (128 used: 256 halves)
    float*        epf = (float*)(smu + EPF_O);  // 64 x 66 (64 used)
    unsigned int* dph = smu + DPH_O;            // 32 x 132
    float*        dpf = (float*)(smu + DPF_O);  // 32 x 66
    unsigned int* vh  = smu + VH_O;             // 32 groups x 4 (3 used)
    float*        vfn = (float*)(smu + VFN_O);  // 64 f32 (-v for c%8 6,7)

    const int b  = blockIdx.z;
    const int d0 = blockIdx.y * 32;
    const int e0 = blockIdx.x * 64;
    const int t  = threadIdx.x;

    const __half* ehsrc = g_enc_h + ((size_t)b * E_ + e0) * 256;
    for (int i = t; i < 64 * 32; i += 256) {
        int r = i >> 5, q = i & 31;
        uint4 s = ((const uint4*)ehsrc)[r * 32 + q];
        *(uint4*)(eph + r * 132 + q * 4) = s;
    }
    // f fills: uint2 (8B) stores — pitch 66 keeps LDS.64 reads conflict-free,
    // and 8B granularity keeps every store aligned (r*66 + q*2 is even).
    const float* efsrc = g_enc_f + ((size_t)b * E_ + e0) * 64;
    for (int i = t; i < 64 * 32; i += 256) {
        int r = i >> 5, q = i & 31;
        uint2 s = ((const uint2*)efsrc)[r * 32 + q];
        *(uint2*)(epf + r * 66 + q * 2) = s;
    }
    const __half* dhsrc = g_dec_h + ((size_t)b * D_ + d0) * 256;
    for (int i = t; i < 32 * 32; i += 256) {
        int r = i >> 5, q = i & 31;
        uint4 s = ((const uint4*)dhsrc)[r * 32 + q];
        *(uint4*)(dph + r * 132 + q * 4) = s;
    }
    const float* dfsrc = g_dec_f + ((size_t)b * D_ + d0) * 64;
    for (int i = t; i < 32 * 32; i += 256) {
        int r = i >> 5, q = i & 31;
        uint2 s = ((const uint2*)dfsrc)[r * 32 + q];
        *(uint2*)(dpf + r * 66 + q * 2) = s;
    }
    if (t < 128) {
        int g = t >> 2, w = t & 3;
        unsigned int val = 0;
        if (w < 3) {
            __half2 p = __floats2half2_rn(v_g[8 * g + 2 * w], v_g[8 * g + 2 * w + 1]);
            val = *reinterpret_cast<unsigned int*>(&p);
        }
        vh[t] = val;
    }
    if (t < 64) {
        vfn[t] = -v_g[8 * (t >> 1) + 6 + (t & 1)];
    }
    __syncthreads();

    const int el = t & 31;
    const int dg = t >> 5;
    const unsigned int* eh0 = eph + el * 132;
    const unsigned int* eh1 = eph + (el + 32) * 132;
    const float* ef0 = epf + el * 66;
    const float* ef1 = epf + (el + 32) * 66;
    const unsigned int* dhb = dph + (dg * 4) * 132;
    const float* dfb = dpf + (dg * 4) * 66;

    __half2 ah[8];
    ull af[8];
    float facc[8];
#pragma unroll
    for (int p = 0; p < 8; p++) {
        ah[p] = __floats2half2_rn(0.f, 0.f);
        af[p] = 0ull;
        facc[p] = 0.f;
    }

    for (int g = 0; g < 32; g++) {
        uint4 vhp = *(const uint4*)(vh + 4 * g);
        __half2 v0 = u2h(vhp.x), v1 = u2h(vhp.y), v2 = u2h(vhp.z);
        ull nv = *(const ull*)(vfn + 2 * g);
        uint4 e0hq = *(const uint4*)(eh0 + 4 * g);
        uint4 e1hq = *(const uint4*)(eh1 + 4 * g);
        ull e0f = *(const ull*)(ef0 + 2 * g);
        ull e1f = *(const ull*)(ef1 + 2 * g);
#pragma unroll
        for (int i = 0; i < 4; i++) {
            uint4 dh = *(const uint4*)(dhb + i * 132 + 4 * g);
            ull df = *(const ull*)(dfb + i * 66 + 2 * g);
            __half2 dh0 = u2h(dh.x), dh1 = u2h(dh.y), dh2 = u2h(dh.z);
            __half2 s0 = ah[i * 2];
            s0 = __hfma2(tanh2h(__hadd2(dh0, u2h(e0hq.x))), v0, s0);
            s0 = __hfma2(tanh2h(__hadd2(dh1, u2h(e0hq.y))), v1, s0);
            s0 = __hfma2(tanh2h(__hadd2(dh2, u2h(e0hq.z))), v2, s0);
            ah[i * 2] = s0;
            __half2 s1 = ah[i * 2 + 1];
            s1 = __hfma2(tanh2h(__hadd2(dh0, u2h(e1hq.x))), v0, s1);
            s1 = __hfma2(tanh2h(__hadd2(dh1, u2h(e1hq.y))), v1, s1);
            s1 = __hfma2(tanh2h(__hadd2(dh2, u2h(e1hq.z))), v2, s1);
            ah[i * 2 + 1] = s1;
            af[i * 2]     = tanh_sum_acc1(df, e0f, nv, af[i * 2]);
            af[i * 2 + 1] = tanh_sum_acc1(df, e1f, nv, af[i * 2 + 1]);
        }
        if ((g & 3) == 3) {
#pragma unroll
            for (int p = 0; p < 8; p++) {
                float2 f = __half22float2(ah[p]);
                facc[p] += f.x + f.y;
                ah[p] = __floats2half2_rn(0.f, 0.f);
            }
        }
    }

#pragma unroll
    for (int p = 0; p < 8; p++) {
        float lo, hi;
        asm("mov.b64 {%0, %1}, %2;" : "=f"(lo), "=f"(hi) : "l"(af[p]));
        facc[p] += lo + hi;
    }

#pragma unroll
    for (int i = 0; i < 4; i++) {
        float* srow = g_scores + ((size_t)b * D_ + d0 + dg * 4 + i) * E_ + e0 + el;
        srow[0]  = facc[i * 2];
        srow[32] = facc[i * 2 + 1];
    }
}

// ---------------------------------------------------------------------------
// Masked log-softmax, one warp per row (E=512, 16 elems/lane).
// ---------------------------------------------------------------------------
__global__ __launch_bounds__(256) void softmax_kernel(const int* __restrict__ mask,
                                                      float* __restrict__ out) {
    const int row  = blockIdx.x * 8 + (threadIdx.x >> 5);
    const int lane = threadIdx.x & 31;

    const float4* s = (const float4*)(g_scores + (size_t)row * E_);
    const int4*   m = (const int4*)(mask + (size_t)row * E_);

    float x[16];
    float vmax = -3.0e38f;
#pragma unroll
    for (int q = 0; q < 4; q++) {
        float4 sv = s[q * 32 + lane];
        int4   mv = m[q * 32 + lane];
        x[4 * q + 0] = mv.x ? sv.x : NEG_INF;
        x[4 * q + 1] = mv.y ? sv.y : NEG_INF;
        x[4 * q + 2] = mv.z ? sv.z : NEG_INF;
        x[4 * q + 3] = mv.w ? sv.w : NEG_INF;
        vmax = fmaxf(vmax, fmaxf(fmaxf(x[4 * q], x[4 * q + 1]),
                                 fmaxf(x[4 * q + 2], x[4 * q + 3])));
    }
#pragma unroll
    for (int o = 16; o; o >>= 1)
        vmax = fmaxf(vmax, __shfl_xor_sync(0xffffffffu, vmax, o));

    float sum = 0.f;
#pragma unroll
    for (int k = 0; k < 16; k++) sum += __expf(x[k] - vmax);
#pragma unroll
    for (int o = 16; o; o >>= 1)
        sum += __shfl_xor_sync(0xffffffffu, sum, o);

    const float lse = vmax + logf(sum);

    float* orow = out + (size_t)row * E_;
#pragma unroll
    for (int q = 0; q < 4; q++) {
        float4 o4 = make_float4(x[4 * q] - lse, x[4 * q + 1] - lse,
                                x[4 * q + 2] - lse, x[4 * q + 3] - lse);
        ((float4*)orow)[q * 32 + lane] = o4;
    }
}

// ---------------------------------------------------------------------------
extern "C" void kernel_launch(void* const* d_in, const int* in_sizes, int n_in,
                              void* d_out, int out_size) {
    const float* decoder = (const float*)d_in[0];
    const float* encoder = (const float*)d_in[1];
    const int*   mask    = (const int*)d_in[2];
    const float* W1      = (const float*)d_in[3];
    const float* W2      = (const float*)d_in[4];
    const float* v       = (const float*)d_in[5];
    float* out           = (float*)d_out;

    cudaFuncSetAttribute(scores_kernel,
                         cudaFuncAttributeMaxDynamicSharedMemorySize, SCORES_SMEM);

    gemm_fused_kernel<<<dim3(8, 12, B_), 128>>>(encoder, decoder, W1, W2);
    scores_kernel<<<dim3(E_ / 64, D_ / 32, B_), 256, SCORES_SMEM>>>(v);
    softmax_kernel<<<B_ * D_ / 8, 256>>>(mask, out);
}